// round 9
// baseline (speedup 1.0000x reference)
#include <cuda_runtime.h>
#include <cuda_fp16.h>
#include <math.h>
#include <stdint.h>

// ---------------------------------------------------------------------------
// ChannelCrossAttention — HMMA fp16 2-term split (A = hi+lo fp16 exact,
// B = single fp16). 128x256 CTA tiles, 64x64 warp tiles, 3-stage cp.async
// pipeline with single sync per chunk, warp-parallel softmax.
// ---------------------------------------------------------------------------

// packed 2xfp16 per u32 everywhere
__device__ uint32_t g_x_h[2u * 32768u * 256u];     // [s][m][kpair]
__device__ uint32_t g_x_l[2u * 32768u * 256u];
__device__ uint32_t g_wq_h[2u * 1536u * 256u];     // [s][c][kpair]
__device__ uint32_t g_wp_h[2u * 512u * 256u];
// q,k channel-major: [s][w(q=0,k=1)][b][c 512][tokenpair 2048]
__device__ uint32_t g_qk_h[2u * 2u * 8u * 512u * 2048u];
__device__ uint32_t g_qk_l[2u * 2u * 8u * 512u * 2048u];   // only q uses lo
// v token-major: [s][b][n 4096][cpair 256]
__device__ uint32_t g_v_h[2u * 8u * 4096u * 256u];
__device__ uint32_t g_v_l[2u * 8u * 4096u * 256u];
// attention out token-major: [s][b][n][kpair 256]
__device__ uint32_t g_att_h[2u * 8u * 4096u * 256u];
__device__ uint32_t g_att_l[2u * 8u * 4096u * 256u];
// per-channel sumsq partials: [s][w][b][c 512][mtile 32]
__device__ float g_nrm[2u * 2u * 8u * 512u * 32u];
// Gram partials [g 128][chunk 8][64*64]
__device__ float g_pgram[128u * 8u * 4096u];
// P packed fp16 [g][d 64][epair 32]
__device__ uint32_t g_p_h[128u * 2048u];

// ---------------------------------------------------------------------------
__device__ __forceinline__ uint32_t smem_u32(const void* p) {
    uint32_t a;
    asm("{ .reg .u64 t; cvta.to.shared.u64 t, %1; cvt.u32.u64 %0, t; }" : "=r"(a) : "l"(p));
    return a;
}
__device__ __forceinline__ uint32_t swz(uint32_t off) { return off ^ ((off >> 3) & 0x70); }

__device__ __forceinline__ void ldmx4(uint32_t& r0, uint32_t& r1, uint32_t& r2, uint32_t& r3,
                                      uint32_t addr) {
    asm volatile("ldmatrix.sync.aligned.m8n8.x4.shared.b16 {%0,%1,%2,%3}, [%4];"
        : "=r"(r0), "=r"(r1), "=r"(r2), "=r"(r3) : "r"(addr));
}
__device__ __forceinline__ void mma_h(float* c, const uint32_t* a, const uint32_t* b) {
    asm volatile("mma.sync.aligned.m16n8k16.row.col.f32.f16.f16.f32 "
        "{%0,%1,%2,%3}, {%4,%5,%6,%7}, {%8,%9}, {%0,%1,%2,%3};"
        : "+f"(c[0]), "+f"(c[1]), "+f"(c[2]), "+f"(c[3])
        : "r"(a[0]), "r"(a[1]), "r"(a[2]), "r"(a[3]), "r"(b[0]), "r"(b[1]));
}
#define CP_ASYNC16(dst, src) \
    asm volatile("cp.async.cg.shared.global [%0], [%1], 16;" :: "r"(dst), "l"(src))
#define CP_COMMIT() asm volatile("cp.async.commit_group;")
#define CP_WAIT0()  asm volatile("cp.async.wait_group 0;")
#define CP_WAIT1()  asm volatile("cp.async.wait_group 1;")

__device__ __forceinline__ uint32_t packh(__half a, __half b) {
    return (uint32_t)__half_as_ushort(a) | ((uint32_t)__half_as_ushort(b) << 16);
}
__device__ __forceinline__ void cvt2h(float a, float b, uint32_t& hi, uint32_t& lo) {
    __half ha = __float2half_rn(a), hb = __float2half_rn(b);
    __half la = __float2half_rn(a - __half2float(ha));
    __half lb = __float2half_rn(b - __half2float(hb));
    hi = packh(ha, hb);
    lo = packh(la, lb);
}
__device__ __forceinline__ uint32_t cvt1h(float a, float b) {
    return packh(__float2half_rn(a), __float2half_rn(b));
}

// qkv/proj smem: stage = A-hi 16K | A-lo 16K | B 32K = 64KB, 3 stages
#define SQ_AHI(st) ((st) * 65536 + 0)
#define SQ_ALO(st) ((st) * 65536 + 16384)
#define SQ_B(st)   ((st) * 65536 + 32768)
#define QKV_SMEM (196608 + 1024)
// gram smem: stage = q-hi 8K | q-lo 8K | k-hi 8K = 24KB, 2 stages
#define SG_QH(st) ((st) * 24576 + 0)
#define SG_QL(st) ((st) * 24576 + 8192)
#define SG_KH(st) ((st) * 24576 + 16384)
#define GRAM_SMEM (49152 + 1024)
// pv smem: v-hi 16K | v-lo 16K | P 8K
#define SP_VH 0
#define SP_VL 16384
#define SP_P  32768
#define PV_SMEM (40960 + 1024)

// ---------------------------------------------------------------------------
// Prep kernels
// ---------------------------------------------------------------------------
__global__ __launch_bounds__(256) void prep_x_kernel(
    const float* __restrict__ x, const float* __restrict__ x_d)
{
    int idx = blockIdx.x * 256 + threadIdx.x;
    int s = idx >> 23;
    int r = idx & 0x7FFFFF;
    int m = r >> 8, kp = r & 255;
    const float* X = s ? x_d : x;
    float2 v = *(const float2*)&X[(size_t)m * 512 + kp * 2];
    uint32_t hi, lo; cvt2h(v.x, v.y, hi, lo);
    g_x_h[idx] = hi; g_x_l[idx] = lo;
}

__global__ __launch_bounds__(256) void prep_w_kernel(
    const float* __restrict__ Wq_r, const float* __restrict__ Wq_T,
    const float* __restrict__ Wp_r, const float* __restrict__ Wp_T)
{
    int idx = blockIdx.x * 256 + threadIdx.x;
    const int TQ = 2 * 1536 * 256;
    const int TP = 2 * 512 * 256;
    if (idx < TQ) {
        int s = idx / (1536 * 256);
        int r = idx % (1536 * 256);
        int c = r >> 8, kp = r & 255;
        const float* W = s ? Wq_T : Wq_r;
        g_wq_h[idx] = cvt1h(W[(size_t)(2 * kp) * 1536 + c],
                            W[(size_t)(2 * kp + 1) * 1536 + c]);
    } else if (idx < TQ + TP) {
        int i2 = idx - TQ;
        int s = i2 / (512 * 256);
        int r = i2 % (512 * 256);
        int c = r >> 8, kp = r & 255;
        const float* W = s ? Wp_T : Wp_r;
        g_wp_h[i2] = cvt1h(W[(size_t)(2 * kp) * 512 + c],
                           W[(size_t)(2 * kp + 1) * 512 + c]);
    }
}

// ---------------------------------------------------------------------------
// Big-tile GEMM core: CTA 128(m) x 256(n), warp 64x64 (wm 2 x wn 4).
// ---------------------------------------------------------------------------
__device__ __forceinline__ void fill_big(uint32_t sb, int st, int tid, int kp0,
    const uint32_t* __restrict__ AH, const uint32_t* __restrict__ AL, size_t aBase,
    const uint32_t* __restrict__ B, size_t bBase)
{
#pragma unroll
    for (int it = 0; it < 4; it++) {
        int idx = tid + it * 256;          // 1024 lines per A region
        int r = idx >> 3, c16 = idx & 7;
        uint32_t dsw = swz((uint32_t)(r * 128 + c16 * 16));
        size_t so = aBase + (size_t)r * 256 + kp0 + c16 * 4;
        CP_ASYNC16(sb + SQ_AHI(st) + dsw, AH + so);
        CP_ASYNC16(sb + SQ_ALO(st) + dsw, AL + so);
    }
#pragma unroll
    for (int it = 0; it < 8; it++) {
        int idx = tid + it * 256;          // 2048 lines for B
        int r = idx >> 3, c16 = idx & 7;
        uint32_t dsw = swz((uint32_t)(r * 128 + c16 * 16));
        CP_ASYNC16(sb + SQ_B(st) + dsw, B + bBase + (size_t)r * 256 + kp0 + c16 * 4);
    }
    CP_COMMIT();
}

__device__ __forceinline__ void mma_big(uint32_t sb, int st, int wm, int wn, int lane,
                                        float acc[4][8][4])
{
    const int aRow  = wm * 64 + (lane & 15);
    const int aColb = (lane >> 4) * 16;
    const int bRow  = wn * 64 + (lane & 7) + ((lane >> 4) & 1) * 8;
    const int bColb = ((lane >> 3) & 1) * 16;
#pragma unroll
    for (int kk = 0; kk < 4; kk++) {
        uint32_t ah[4][4], al[4][4], bf[8][2];
#pragma unroll
        for (int mt = 0; mt < 4; mt++) {
            ldmx4(ah[mt][0], ah[mt][1], ah[mt][2], ah[mt][3],
                  sb + SQ_AHI(st) + swz((uint32_t)((aRow + mt * 16) * 128 + aColb + kk * 32)));
            ldmx4(al[mt][0], al[mt][1], al[mt][2], al[mt][3],
                  sb + SQ_ALO(st) + swz((uint32_t)((aRow + mt * 16) * 128 + aColb + kk * 32)));
        }
#pragma unroll
        for (int j = 0; j < 4; j++)
            ldmx4(bf[2 * j][0], bf[2 * j][1], bf[2 * j + 1][0], bf[2 * j + 1][1],
                  sb + SQ_B(st) + swz((uint32_t)((bRow + j * 16) * 128 + bColb + kk * 32)));
#pragma unroll
        for (int mt = 0; mt < 4; mt++)
#pragma unroll
            for (int nj = 0; nj < 8; nj++) {
                mma_h(acc[mt][nj], ah[mt], bf[nj]);
                mma_h(acc[mt][nj], al[mt], bf[nj]);
            }
    }
}

// ---------------------------------------------------------------------------
// Kernel 1: qkv GEMM.  grid (cTile 6, mTile 256, s 2)
// ---------------------------------------------------------------------------
__global__ __launch_bounds__(256, 1) void qkv_mma_kernel()
{
    extern __shared__ char dsm[];
    uint32_t sbr = smem_u32(dsm);
    uint32_t sb = (sbr + 1023) & ~1023u;
    char* ab = dsm + (sb - sbr);

    const int tid = threadIdx.x;
    const int wid = tid >> 5;
    const int lane = tid & 31;
    const int wm = wid & 1, wn = wid >> 1;
    const int s = blockIdx.z;
    const int m0 = blockIdx.y * 128;
    const int c0 = blockIdx.x * 256;
    const int b = m0 >> 12, n0 = m0 & 4095;
    const int which = c0 >> 9;          // 0=q 1=k 2=v

    const size_t aBase = ((size_t)s * 32768 + m0) * 256;
    const size_t bBase = ((size_t)s * 1536 + c0) * 256;

    float acc[4][8][4];
#pragma unroll
    for (int i = 0; i < 4; i++)
#pragma unroll
        for (int j = 0; j < 8; j++)
#pragma unroll
            for (int r = 0; r < 4; r++) acc[i][j][r] = 0.f;

    fill_big(sb, 0, tid, 0, g_x_h, g_x_l, aBase, g_wq_h, bBase);
    fill_big(sb, 1, tid, 32, g_x_h, g_x_l, aBase, g_wq_h, bBase);
    for (int c = 0; c < 8; c++) {
        if (c < 7) CP_WAIT1(); else CP_WAIT0();
        __syncthreads();
        if (c + 2 < 8)
            fill_big(sb, (c + 2) % 3, tid, (c + 2) * 32, g_x_h, g_x_l, aBase, g_wq_h, bBase);
        mma_big(sb, c % 3, wm, wn, lane, acc);
    }
    __syncthreads();

    if (which == 2) {
        // v: pack channel-pairs from frags -> token-major [n][cpair]
        const size_t vb = (size_t)(s * 8 + b) * 4096;
        const int cb = c0 - 1024;
#pragma unroll
        for (int mt = 0; mt < 4; mt++) {
            int t = n0 + wm * 64 + mt * 16 + (lane >> 2);
#pragma unroll
            for (int nj = 0; nj < 8; nj++) {
                int cp = (cb + wn * 64 + nj * 8 + 2 * (lane & 3)) >> 1;
                uint32_t h0, l0, h1, l1;
                cvt2h(acc[mt][nj][0], acc[mt][nj][1], h0, l0);
                cvt2h(acc[mt][nj][2], acc[mt][nj][3], h1, l1);
                size_t a0 = (vb + t) * 256 + cp;
                g_v_h[a0] = h0; g_v_l[a0] = l0;
                size_t a1 = a0 + 8 * 256;
                g_v_h[a1] = h1; g_v_l[a1] = l1;
            }
        }
    } else {
        // q/k: channel-major token-pairs via smem transpose + exact norms
        float* sT = (float*)ab;   // 64 x 136 fp32
#pragma unroll
        for (int p = 0; p < 4; p++) {
            if (wn == p) {
#pragma unroll
                for (int mt = 0; mt < 4; mt++)
#pragma unroll
                    for (int nj = 0; nj < 8; nj++) {
                        int m = wm * 64 + mt * 16 + (lane >> 2);
                        int cl = nj * 8 + 2 * (lane & 3);
                        sT[cl * 136 + m]           = acc[mt][nj][0];
                        sT[(cl + 1) * 136 + m]     = acc[mt][nj][1];
                        sT[cl * 136 + m + 8]       = acc[mt][nj][2];
                        sT[(cl + 1) * 136 + m + 8] = acc[mt][nj][3];
                    }
            }
            __syncthreads();
#pragma unroll
            for (int it = 0; it < 8; it++) {
                int idx = tid + it * 256;
                int row = idx >> 5;            // 0..63 (warp-uniform)
                int m4 = (idx & 31) * 4;       // lane*4
                float4 vv = *(float4*)&sT[row * 136 + m4];
                int c = c0 + p * 64 + row;
                int rem = c & 511;
                uint32_t h0, l0, h1, l1;
                cvt2h(vv.x, vv.y, h0, l0);
                cvt2h(vv.z, vv.w, h1, l1);
                size_t rowb = ((size_t)((s * 2 + which) * 8 + b) * 512 + rem) * 2048;
                *(uint2*)&g_qk_h[rowb + ((n0 + m4) >> 1)] = make_uint2(h0, h1);
                if (which == 0)
                    *(uint2*)&g_qk_l[rowb + ((n0 + m4) >> 1)] = make_uint2(l0, l1);
                float r2 = vv.x * vv.x + vv.y * vv.y + vv.z * vv.z + vv.w * vv.w;
                r2 += __shfl_xor_sync(0xFFFFFFFFu, r2, 16);
                r2 += __shfl_xor_sync(0xFFFFFFFFu, r2, 8);
                r2 += __shfl_xor_sync(0xFFFFFFFFu, r2, 4);
                r2 += __shfl_xor_sync(0xFFFFFFFFu, r2, 2);
                r2 += __shfl_xor_sync(0xFFFFFFFFu, r2, 1);
                if (lane == 0)
                    g_nrm[(((size_t)(s * 2 + which) * 8 + b) * 512 + rem) * 32 + (n0 >> 7)] = r2;
            }
            __syncthreads();
        }
    }
}

// ---------------------------------------------------------------------------
// Kernel 2a: Gram partials (2-term fp16), double-buffered.
// grid (chunk 8, bh 64, s 2)
// ---------------------------------------------------------------------------
__global__ __launch_bounds__(256) void attn_gram_kernel()
{
    extern __shared__ char dsm[];
    uint32_t sbr = smem_u32(dsm);
    uint32_t sb = (sbr + 1023) & ~1023u;

    const int tid = threadIdx.x;
    const int wid = tid >> 5;
    const int lane = tid & 31;
    const int wm = wid & 1, wn = wid >> 1;
    const int chunk = blockIdx.x;
    const int bh = blockIdx.y;
    const int s = blockIdx.z;
    const int b = bh >> 3, h = bh & 7;
    const int so = s ^ 1;
    const int g = s * 64 + bh;

    const size_t qrow = ((size_t)(s  * 2 + 0) * 8 + b) * 512 + h * 64;
    const size_t krow = ((size_t)(so * 2 + 1) * 8 + b) * 512 + h * 64;

    float acc[2][2][4];
#pragma unroll
    for (int i = 0; i < 2; i++)
#pragma unroll
        for (int j = 0; j < 2; j++)
#pragma unroll
            for (int r = 0; r < 4; r++) acc[i][j][r] = 0.f;

    const int aRow  = wm * 32 + (lane & 15);
    const int aColb = (lane >> 4) * 16;
    const int bRow  = wn * 16 + (lane & 7) + ((lane >> 4) & 1) * 8;
    const int bColb = ((lane >> 3) & 1) * 16;

    auto fill_sub = [&](int st, int sub) {
        int tp0 = chunk * 256 + sub * 32;
#pragma unroll
        for (int it = 0; it < 2; it++) {
            int idx = tid + it * 256;
            int r = idx >> 3, c16 = idx & 7;
            uint32_t dsw = swz((uint32_t)(r * 128 + c16 * 16));
            size_t qa = (qrow + r) * 2048 + tp0 + c16 * 4;
            size_t ka = (krow + r) * 2048 + tp0 + c16 * 4;
            CP_ASYNC16(sb + SG_QH(st) + dsw, g_qk_h + qa);
            CP_ASYNC16(sb + SG_QL(st) + dsw, g_qk_l + qa);
            CP_ASYNC16(sb + SG_KH(st) + dsw, g_qk_h + ka);
        }
        CP_COMMIT();
    };

    fill_sub(0, 0);
    for (int sub = 0; sub < 8; sub++) {
        int st = sub & 1;
        if (sub < 7) fill_sub(st ^ 1, sub + 1);
        if (sub < 7) CP_WAIT1(); else CP_WAIT0();
        __syncthreads();
#pragma unroll
        for (int kk = 0; kk < 4; kk++) {
            uint32_t qh[2][4], ql[2][4], kf[2][2];
#pragma unroll
            for (int mt = 0; mt < 2; mt++) {
                ldmx4(qh[mt][0], qh[mt][1], qh[mt][2], qh[mt][3],
                      sb + SG_QH(st) + swz((uint32_t)((aRow + mt * 16) * 128 + aColb + kk * 32)));
                ldmx4(ql[mt][0], ql[mt][1], ql[mt][2], ql[mt][3],
                      sb + SG_QL(st) + swz((uint32_t)((aRow + mt * 16) * 128 + aColb + kk * 32)));
            }
            ldmx4(kf[0][0], kf[0][1], kf[1][0], kf[1][1],
                  sb + SG_KH(st) + swz((uint32_t)(bRow * 128 + bColb + kk * 32)));
#pragma unroll
            for (int mt = 0; mt < 2; mt++)
#pragma unroll
                for (int nt = 0; nt < 2; nt++) {
                    mma_h(acc[mt][nt], qh[mt], kf[nt]);
                    mma_h(acc[mt][nt], ql[mt], kf[nt]);
                }
        }
        __syncthreads();
    }

    const size_t base = (size_t)(g * 8 + chunk) * 4096;
#pragma unroll
    for (int mt = 0; mt < 2; mt++)
#pragma unroll
        for (int nt = 0; nt < 2; nt++) {
            int m = wm * 32 + mt * 16 + (lane >> 2);
            int col = wn * 16 + nt * 8 + 2 * (lane & 3);
            *(float2*)&g_pgram[base + m * 64 + col] = make_float2(acc[mt][nt][0], acc[mt][nt][1]);
            *(float2*)&g_pgram[base + (m + 8) * 64 + col] = make_float2(acc[mt][nt][2], acc[mt][nt][3]);
        }
}

// ---------------------------------------------------------------------------
// Kernel 2b: reduce partials + norms, softmax (warp-parallel), emit P fp16
// ---------------------------------------------------------------------------
__global__ __launch_bounds__(256) void attn_softmax_kernel(
    const float* __restrict__ temp_rgb, const float* __restrict__ temp_T)
{
    const int g = blockIdx.x;
    const int s = g >> 6;
    const int bh = g & 63;
    const int b = bh >> 3, h = bh & 7;
    const int so = s ^ 1;
    const float temp = (s ? temp_T : temp_rgb)[h];

    __shared__ float qinv[64], kinv[64];
    const int tid = threadIdx.x;

    if (tid < 64) {
        float sq = 0.f;
        size_t nb = (((size_t)(s * 2 + 0) * 8 + b) * 512 + h * 64 + tid) * 32;
#pragma unroll
        for (int t = 0; t < 32; t++) sq += g_nrm[nb + t];
        qinv[tid] = 1.f / fmaxf(sqrtf(sq), 1e-12f);
    } else if (tid < 128) {
        float sk = 0.f;
        size_t nb = (((size_t)(so * 2 + 1) * 8 + b) * 512 + h * 64 + tid - 64) * 32;
#pragma unroll
        for (int t = 0; t < 32; t++) sk += g_nrm[nb + t];
        kinv[tid - 64] = 1.f / fmaxf(sqrtf(sk), 1e-12f);
    }
    __syncthreads();

    const int wid = tid >> 5, lane = tid & 31;
    const int j0 = lane * 2;
    const float ki0 = kinv[j0], ki1 = kinv[j0 + 1];
#pragma unroll
    for (int r = 0; r < 8; r++) {
        int d = wid * 8 + r;
        float v0 = 0.f, v1 = 0.f;
#pragma unroll
        for (int c = 0; c < 8; c++) {
            float2 pv = *(const float2*)&g_pgram[(size_t)(g * 8 + c) * 4096 + d * 64 + j0];
            v0 += pv.x; v1 += pv.y;
        }
        float sc = temp * qinv[d];
        v0 *= sc * ki0;
        v1 *= sc * ki1;
        float mx = fmaxf(v0, v1);
#pragma unroll
        for (int o = 16; o; o >>= 1) mx = fmaxf(mx, __shfl_xor_sync(0xFFFFFFFFu, mx, o));
        float e0 = __expf(v0 - mx), e1 = __expf(v1 - mx);
        float sm = e0 + e1;
#pragma unroll
        for (int o = 16; o; o >>= 1) sm += __shfl_xor_sync(0xFFFFFFFFu, sm, o);
        float inv = 1.f / sm;
        g_p_h[(size_t)g * 2048 + d * 32 + lane] = cvt1h(e0 * inv, e1 * inv);
    }
}

// ---------------------------------------------------------------------------
// Kernel 2c: out = P @ v (2-term on v, P single). grid (tile 32, bh 64, s 2)
// ---------------------------------------------------------------------------
__global__ __launch_bounds__(256) void attn_pv_kernel()
{
    extern __shared__ char dsm[];
    uint32_t sbr = smem_u32(dsm);
    uint32_t sb = (sbr + 1023) & ~1023u;

    const int tid = threadIdx.x;
    const int wid = tid >> 5;
    const int lane = tid & 31;
    const int wm = wid & 1, wn = wid >> 1;
    const int n0 = blockIdx.x * 128;
    const int bh = blockIdx.y;
    const int s = blockIdx.z;
    const int b = bh >> 3, h = bh & 7;
    const int so = s ^ 1;
    const int g = s * 64 + bh;
    const size_t vb = (size_t)(so * 8 + b) * 4096;

#pragma unroll
    for (int it = 0; it < 4; it++) {
        int idx = tid + it * 256;
        int r = idx >> 3, c16 = idx & 7;
        uint32_t dsw = swz((uint32_t)(r * 128 + c16 * 16));
        size_t va = (vb + n0 + r) * 256 + h * 32 + c16 * 4;
        CP_ASYNC16(sb + SP_VH + dsw, g_v_h + va);
        CP_ASYNC16(sb + SP_VL + dsw, g_v_l + va);
    }
#pragma unroll
    for (int it = 0; it < 2; it++) {
        int idx = tid + it * 256;
        int r = idx >> 3, c16 = idx & 7;
        uint32_t dsw = swz((uint32_t)(r * 128 + c16 * 16));
        CP_ASYNC16(sb + SP_P + dsw, g_p_h + (size_t)g * 2048 + r * 32 + c16 * 4);
    }
    CP_COMMIT();
    CP_WAIT0();
    __syncthreads();

    float acc[4][2][4];
#pragma unroll
    for (int i = 0; i < 4; i++)
#pragma unroll
        for (int j = 0; j < 2; j++)
#pragma unroll
            for (int r = 0; r < 4; r++) acc[i][j][r] = 0.f;

    const int aRow  = wm * 64 + (lane & 15);
    const int aColb = (lane >> 4) * 16;
    const int bRow  = wn * 16 + (lane & 7) + ((lane >> 4) & 1) * 8;
    const int bColb = ((lane >> 3) & 1) * 16;

#pragma unroll
    for (int kk = 0; kk < 4; kk++) {
        uint32_t vh[4][4], vl[4][4], pf[2][2];
#pragma unroll
        for (int mt = 0; mt < 4; mt++) {
            ldmx4(vh[mt][0], vh[mt][1], vh[mt][2], vh[mt][3],
                  sb + SP_VH + swz((uint32_t)((aRow + mt * 16) * 128 + aColb + kk * 32)));
            ldmx4(vl[mt][0], vl[mt][1], vl[mt][2], vl[mt][3],
                  sb + SP_VL + swz((uint32_t)((aRow + mt * 16) * 128 + aColb + kk * 32)));
        }
        ldmx4(pf[0][0], pf[0][1], pf[1][0], pf[1][1],
              sb + SP_P + swz((uint32_t)(bRow * 128 + bColb + kk * 32)));
#pragma unroll
        for (int mt = 0; mt < 4; mt++)
#pragma unroll
            for (int nt = 0; nt < 2; nt++) {
                mma_h(acc[mt][nt], vh[mt], pf[nt]);
                mma_h(acc[mt][nt], vl[mt], pf[nt]);
            }
    }

    const size_t ob = (size_t)(s * 8 + b) * 4096;
#pragma unroll
    for (int mt = 0; mt < 4; mt++) {
        int t = n0 + wm * 64 + mt * 16 + (lane >> 2);
#pragma unroll
        for (int nt = 0; nt < 2; nt++) {
            int dp = wn * 8 + nt * 4 + (lane & 3);
            uint32_t h0, l0, h1, l1;
            cvt2h(acc[mt][nt][0], acc[mt][nt][1], h0, l0);
            cvt2h(acc[mt][nt][2], acc[mt][nt][3], h1, l1);
            size_t a0 = (ob + t) * 256 + h * 32 + dp;
            g_att_h[a0] = h0; g_att_l[a0] = l0;
            size_t a1 = a0 + 8 * 256;
            g_att_h[a1] = h1; g_att_l[a1] = l1;
        }
    }
}

// ---------------------------------------------------------------------------
// Kernel 3: proj GEMM. grid (cTile 2, nTile 32, sb 16)
// ---------------------------------------------------------------------------
__global__ __launch_bounds__(256, 1) void proj_mma_kernel(
    const float* __restrict__ br, const float* __restrict__ bt,
    float* __restrict__ out)
{
    extern __shared__ char dsm[];
    uint32_t sbr = smem_u32(dsm);
    uint32_t sb = (sbr + 1023) & ~1023u;
    char* ab = dsm + (sb - sbr);

    const int tid = threadIdx.x;
    const int wid = tid >> 5;
    const int lane = tid & 31;
    const int wm = wid & 1, wn = wid >> 1;
    const int z = blockIdx.z;
    const int s = z >> 3, b = z & 7;
    const float* __restrict__ bias = s ? bt : br;
    const int n0 = blockIdx.y * 128;
    const int c0 = blockIdx.x * 256;

    const size_t aBase = (((size_t)(s * 8 + b)) * 4096 + n0) * 256;
    const size_t bBase = ((size_t)s * 512 + c0) * 256;

    float acc[4][8][4];
#pragma unroll
    for (int i = 0; i < 4; i++)
#pragma unroll
        for (int j = 0; j < 8; j++)
#pragma unroll
            for (int r = 0; r < 4; r++) acc[i][j][r] = 0.f;

    fill_big(sb, 0, tid, 0, g_att_h, g_att_l, aBase, g_wp_h, bBase);
    fill_big(sb, 1, tid, 32, g_att_h, g_att_l, aBase, g_wp_h, bBase);
    for (int c = 0; c < 8; c++) {
        if (c < 7) CP_WAIT1(); else CP_WAIT0();
        __syncthreads();
        if (c + 2 < 8)
            fill_big(sb, (c + 2) % 3, tid, (c + 2) * 32, g_att_h, g_att_l, aBase, g_wp_h, bBase);
        mma_big(sb, c % 3, wm, wn, lane, acc);
    }
    __syncthreads();

    // epilogue: [token][channel] + bias via smem transpose (2 passes over wm)
    float* sT = (float*)ab;   // 64 x 264 fp32
    float* outp = out + (size_t)(s * 8 + b) * 2097152;
#pragma unroll
    for (int p = 0; p < 2; p++) {
        if (wm == p) {
#pragma unroll
            for (int mt = 0; mt < 4; mt++)
#pragma unroll
                for (int nj = 0; nj < 8; nj++) {
                    int m = mt * 16 + (lane >> 2);
                    int cc = wn * 64 + nj * 8 + 2 * (lane & 3);
                    sT[m * 264 + cc]           = acc[mt][nj][0];
                    sT[m * 264 + cc + 1]       = acc[mt][nj][1];
                    sT[(m + 8) * 264 + cc]     = acc[mt][nj][2];
                    sT[(m + 8) * 264 + cc + 1] = acc[mt][nj][3];
                }
        }
        __syncthreads();
#pragma unroll
        for (int it = 0; it < 16; it++) {
            int idx = tid + it * 256;
            int row = idx >> 6, ch4 = (idx & 63) * 4;
            int tok = n0 + p * 64 + row;
            float4 vv = *(float4*)&sT[row * 264 + ch4];
            float4 bb = *(const float4*)&bias[c0 + ch4];
            vv.x += bb.x; vv.y += bb.y; vv.z += bb.z; vv.w += bb.w;
            *(float4*)&outp[(size_t)tok * 512 + c0 + ch4] = vv;
        }
        __syncthreads();
    }
}

// ---------------------------------------------------------------------------
extern "C" void kernel_launch(void* const* d_in, const int* in_sizes, int n_in,
                              void* d_out, int out_size)
{
    const float* x        = (const float*)d_in[0];
    const float* x_d      = (const float*)d_in[1];
    const float* W_qkv_r  = (const float*)d_in[2];
    const float* W_qkv_T  = (const float*)d_in[3];
    const float* temp_r   = (const float*)d_in[4];
    const float* temp_T   = (const float*)d_in[5];
    const float* W_proj_r = (const float*)d_in[6];
    const float* b_proj_r = (const float*)d_in[7];
    const float* W_proj_T = (const float*)d_in[8];
    const float* b_proj_T = (const float*)d_in[9];
    float* out = (float*)d_out;

    cudaFuncSetAttribute(qkv_mma_kernel,
        cudaFuncAttributeMaxDynamicSharedMemorySize, QKV_SMEM);
    cudaFuncSetAttribute(proj_mma_kernel,
        cudaFuncAttributeMaxDynamicSharedMemorySize, QKV_SMEM);
    cudaFuncSetAttribute(attn_gram_kernel,
        cudaFuncAttributeMaxDynamicSharedMemorySize, GRAM_SMEM);
    cudaFuncSetAttribute(attn_pv_kernel,
        cudaFuncAttributeMaxDynamicSharedMemorySize, PV_SMEM);

    prep_x_kernel<<<65536, 256>>>(x, x_d);
    prep_w_kernel<<<4096, 256>>>(W_qkv_r, W_qkv_T, W_proj_r, W_proj_T);

    {
        dim3 grid(6, 256, 2);     // c-tile fastest -> A slice L2-reused
        qkv_mma_kernel<<<grid, 256, QKV_SMEM>>>();
    }
    {
        dim3 g1(8, 64, 2);
        attn_gram_kernel<<<g1, 256, GRAM_SMEM>>>();
        attn_softmax_kernel<<<128, 256>>>(temp_r, temp_T);
        dim3 g2(32, 64, 2);
        attn_pv_kernel<<<g2, 256, PV_SMEM>>>();
    }
    {
        dim3 grid(2, 32, 16);     // c-tile fastest
        proj_mma_kernel<<<grid, 256, QKV_SMEM>>>(b_proj_r, b_proj_T, out);
    }
}

// round 10
// speedup vs baseline: 1.5960x; 1.5960x over previous
#include <cuda_runtime.h>
#include <cuda_fp16.h>
#include <math.h>
#include <stdint.h>

// ---------------------------------------------------------------------------
// ChannelCrossAttention — HMMA fp16 1-term (all operands fp16 RN-rounded;
// l2-norms computed exactly from fp32 accumulators). 128x256 CTA tiles,
// 64x64 warp tiles, 3-stage cp.async pipeline.
// ---------------------------------------------------------------------------

// packed 2xfp16 per u32 everywhere
__device__ uint32_t g_x_h[2u * 32768u * 256u];     // [s][m][kpair]
__device__ uint32_t g_wq_h[2u * 1536u * 256u];     // [s][c][kpair]
__device__ uint32_t g_wp_h[2u * 512u * 256u];
// q,k channel-major: [s][w(q=0,k=1)][b][c 512][tokenpair 2048]
__device__ uint32_t g_qk_h[2u * 2u * 8u * 512u * 2048u];
// v token-major: [s][b][n 4096][cpair 256]
__device__ uint32_t g_v_h[2u * 8u * 4096u * 256u];
// attention out token-major: [s][b][n][kpair 256]
__device__ uint32_t g_att_h[2u * 8u * 4096u * 256u];
// per-channel sumsq partials: [s][w][b][c 512][mtile 32]
__device__ float g_nrm[2u * 2u * 8u * 512u * 32u];
// Gram partials [g 128][chunk 8][64*64]
__device__ float g_pgram[128u * 8u * 4096u];
// P packed fp16 [g][d 64][epair 32]
__device__ uint32_t g_p_h[128u * 2048u];

// ---------------------------------------------------------------------------
__device__ __forceinline__ uint32_t smem_u32(const void* p) {
    uint32_t a;
    asm("{ .reg .u64 t; cvta.to.shared.u64 t, %1; cvt.u32.u64 %0, t; }" : "=r"(a) : "l"(p));
    return a;
}
__device__ __forceinline__ uint32_t swz(uint32_t off) { return off ^ ((off >> 3) & 0x70); }

__device__ __forceinline__ void ldmx4(uint32_t& r0, uint32_t& r1, uint32_t& r2, uint32_t& r3,
                                      uint32_t addr) {
    asm volatile("ldmatrix.sync.aligned.m8n8.x4.shared.b16 {%0,%1,%2,%3}, [%4];"
        : "=r"(r0), "=r"(r1), "=r"(r2), "=r"(r3) : "r"(addr));
}
__device__ __forceinline__ void mma_h(float* c, const uint32_t* a, const uint32_t* b) {
    asm volatile("mma.sync.aligned.m16n8k16.row.col.f32.f16.f16.f32 "
        "{%0,%1,%2,%3}, {%4,%5,%6,%7}, {%8,%9}, {%0,%1,%2,%3};"
        : "+f"(c[0]), "+f"(c[1]), "+f"(c[2]), "+f"(c[3])
        : "r"(a[0]), "r"(a[1]), "r"(a[2]), "r"(a[3]), "r"(b[0]), "r"(b[1]));
}
#define CP_ASYNC16(dst, src) \
    asm volatile("cp.async.cg.shared.global [%0], [%1], 16;" :: "r"(dst), "l"(src))
#define CP_COMMIT() asm volatile("cp.async.commit_group;")
#define CP_WAIT0()  asm volatile("cp.async.wait_group 0;")
#define CP_WAIT1()  asm volatile("cp.async.wait_group 1;")

__device__ __forceinline__ uint32_t packh(__half a, __half b) {
    return (uint32_t)__half_as_ushort(a) | ((uint32_t)__half_as_ushort(b) << 16);
}
__device__ __forceinline__ uint32_t cvt1h(float a, float b) {
    return packh(__float2half_rn(a), __float2half_rn(b));
}

// qkv/proj smem: stage = A 16K | B 32K = 48KB, 3 stages
#define SQ_A(st) ((st) * 49152 + 0)
#define SQ_B(st) ((st) * 49152 + 16384)
#define QKV_SMEM (147456 + 1024)
// gram smem: stage = q 8K | k 8K = 16KB, 2 stages
#define SG_Q(st) ((st) * 16384 + 0)
#define SG_K(st) ((st) * 16384 + 8192)
#define GRAM_SMEM (32768 + 1024)
// pv smem: v 16K | P 8K
#define SP_V 0
#define SP_P 16384
#define PV_SMEM (24576 + 1024)

// ---------------------------------------------------------------------------
// Prep kernels
// ---------------------------------------------------------------------------
__global__ __launch_bounds__(256) void prep_x_kernel(
    const float* __restrict__ x, const float* __restrict__ x_d)
{
    int idx = blockIdx.x * 256 + threadIdx.x;
    int s = idx >> 23;
    int r = idx & 0x7FFFFF;
    int m = r >> 8, kp = r & 255;
    const float* X = s ? x_d : x;
    float2 v = *(const float2*)&X[(size_t)m * 512 + kp * 2];
    g_x_h[idx] = cvt1h(v.x, v.y);
}

__global__ __launch_bounds__(256) void prep_w_kernel(
    const float* __restrict__ Wq_r, const float* __restrict__ Wq_T,
    const float* __restrict__ Wp_r, const float* __restrict__ Wp_T)
{
    int idx = blockIdx.x * 256 + threadIdx.x;
    const int TQ = 2 * 1536 * 256;
    const int TP = 2 * 512 * 256;
    if (idx < TQ) {
        int s = idx / (1536 * 256);
        int r = idx % (1536 * 256);
        int c = r >> 8, kp = r & 255;
        const float* W = s ? Wq_T : Wq_r;
        g_wq_h[idx] = cvt1h(W[(size_t)(2 * kp) * 1536 + c],
                            W[(size_t)(2 * kp + 1) * 1536 + c]);
    } else if (idx < TQ + TP) {
        int i2 = idx - TQ;
        int s = i2 / (512 * 256);
        int r = i2 % (512 * 256);
        int c = r >> 8, kp = r & 255;
        const float* W = s ? Wp_T : Wp_r;
        g_wp_h[i2] = cvt1h(W[(size_t)(2 * kp) * 512 + c],
                           W[(size_t)(2 * kp + 1) * 512 + c]);
    }
}

// ---------------------------------------------------------------------------
// Big-tile GEMM core: CTA 128(m) x 256(n), warp 64x64 (wm 2 x wn 4).
// ---------------------------------------------------------------------------
__device__ __forceinline__ void fill_big(uint32_t sb, int st, int tid, int kp0,
    const uint32_t* __restrict__ A, size_t aBase,
    const uint32_t* __restrict__ B, size_t bBase)
{
#pragma unroll
    for (int it = 0; it < 4; it++) {
        int idx = tid + it * 256;          // 1024 lines for A
        int r = idx >> 3, c16 = idx & 7;
        uint32_t dsw = swz((uint32_t)(r * 128 + c16 * 16));
        CP_ASYNC16(sb + SQ_A(st) + dsw, A + aBase + (size_t)r * 256 + kp0 + c16 * 4);
    }
#pragma unroll
    for (int it = 0; it < 8; it++) {
        int idx = tid + it * 256;          // 2048 lines for B
        int r = idx >> 3, c16 = idx & 7;
        uint32_t dsw = swz((uint32_t)(r * 128 + c16 * 16));
        CP_ASYNC16(sb + SQ_B(st) + dsw, B + bBase + (size_t)r * 256 + kp0 + c16 * 4);
    }
    CP_COMMIT();
}

__device__ __forceinline__ void mma_big(uint32_t sb, int st, int wm, int wn, int lane,
                                        float acc[4][8][4])
{
    const int aRow  = wm * 64 + (lane & 15);
    const int aColb = (lane >> 4) * 16;
    const int bRow  = wn * 64 + (lane & 7) + ((lane >> 4) & 1) * 8;
    const int bColb = ((lane >> 3) & 1) * 16;
#pragma unroll
    for (int kk = 0; kk < 4; kk++) {
        uint32_t ah[4][4], bf[8][2];
#pragma unroll
        for (int mt = 0; mt < 4; mt++)
            ldmx4(ah[mt][0], ah[mt][1], ah[mt][2], ah[mt][3],
                  sb + SQ_A(st) + swz((uint32_t)((aRow + mt * 16) * 128 + aColb + kk * 32)));
#pragma unroll
        for (int j = 0; j < 4; j++)
            ldmx4(bf[2 * j][0], bf[2 * j][1], bf[2 * j + 1][0], bf[2 * j + 1][1],
                  sb + SQ_B(st) + swz((uint32_t)((bRow + j * 16) * 128 + bColb + kk * 32)));
#pragma unroll
        for (int mt = 0; mt < 4; mt++)
#pragma unroll
            for (int nj = 0; nj < 8; nj++)
                mma_h(acc[mt][nj], ah[mt], bf[nj]);
    }
}

// ---------------------------------------------------------------------------
// Kernel 1: qkv GEMM.  grid (cTile 6, mTile 256, s 2)
// ---------------------------------------------------------------------------
__global__ __launch_bounds__(256, 1) void qkv_mma_kernel()
{
    extern __shared__ char dsm[];
    uint32_t sbr = smem_u32(dsm);
    uint32_t sb = (sbr + 1023) & ~1023u;
    char* ab = dsm + (sb - sbr);

    const int tid = threadIdx.x;
    const int wid = tid >> 5;
    const int lane = tid & 31;
    const int wm = wid & 1, wn = wid >> 1;
    const int s = blockIdx.z;
    const int m0 = blockIdx.y * 128;
    const int c0 = blockIdx.x * 256;
    const int b = m0 >> 12, n0 = m0 & 4095;
    const int which = c0 >> 9;          // 0=q 1=k 2=v

    const size_t aBase = ((size_t)s * 32768 + m0) * 256;
    const size_t bBase = ((size_t)s * 1536 + c0) * 256;

    float acc[4][8][4];
#pragma unroll
    for (int i = 0; i < 4; i++)
#pragma unroll
        for (int j = 0; j < 8; j++)
#pragma unroll
            for (int r = 0; r < 4; r++) acc[i][j][r] = 0.f;

    fill_big(sb, 0, tid, 0, g_x_h, aBase, g_wq_h, bBase);
    fill_big(sb, 1, tid, 32, g_x_h, aBase, g_wq_h, bBase);
    for (int c = 0; c < 8; c++) {
        if (c < 7) CP_WAIT1(); else CP_WAIT0();
        __syncthreads();
        if (c + 2 < 8)
            fill_big(sb, (c + 2) % 3, tid, (c + 2) * 32, g_x_h, aBase, g_wq_h, bBase);
        mma_big(sb, c % 3, wm, wn, lane, acc);
    }
    __syncthreads();

    if (which == 2) {
        // v: pack channel-pairs from frags -> token-major [n][cpair]
        const size_t vb = (size_t)(s * 8 + b) * 4096;
        const int cb = c0 - 1024;
#pragma unroll
        for (int mt = 0; mt < 4; mt++) {
            int t = n0 + wm * 64 + mt * 16 + (lane >> 2);
#pragma unroll
            for (int nj = 0; nj < 8; nj++) {
                int cp = (cb + wn * 64 + nj * 8 + 2 * (lane & 3)) >> 1;
                size_t a0 = (vb + t) * 256 + cp;
                g_v_h[a0]           = cvt1h(acc[mt][nj][0], acc[mt][nj][1]);
                g_v_h[a0 + 8 * 256] = cvt1h(acc[mt][nj][2], acc[mt][nj][3]);
            }
        }
    } else {
        // q/k: channel-major token-pairs via smem transpose + exact norms
        float* sT = (float*)ab;   // 64 x 136 fp32
#pragma unroll
        for (int p = 0; p < 4; p++) {
            if (wn == p) {
#pragma unroll
                for (int mt = 0; mt < 4; mt++)
#pragma unroll
                    for (int nj = 0; nj < 8; nj++) {
                        int m = wm * 64 + mt * 16 + (lane >> 2);
                        int cl = nj * 8 + 2 * (lane & 3);
                        sT[cl * 136 + m]           = acc[mt][nj][0];
                        sT[(cl + 1) * 136 + m]     = acc[mt][nj][1];
                        sT[cl * 136 + m + 8]       = acc[mt][nj][2];
                        sT[(cl + 1) * 136 + m + 8] = acc[mt][nj][3];
                    }
            }
            __syncthreads();
#pragma unroll
            for (int it = 0; it < 8; it++) {
                int idx = tid + it * 256;
                int row = idx >> 5;            // 0..63 (warp-uniform)
                int m4 = (idx & 31) * 4;       // lane*4
                float4 vv = *(float4*)&sT[row * 136 + m4];
                int c = c0 + p * 64 + row;
                int rem = c & 511;
                uint32_t h0 = cvt1h(vv.x, vv.y);
                uint32_t h1 = cvt1h(vv.z, vv.w);
                size_t rowb = ((size_t)((s * 2 + which) * 8 + b) * 512 + rem) * 2048;
                *(uint2*)&g_qk_h[rowb + ((n0 + m4) >> 1)] = make_uint2(h0, h1);
                float r2 = vv.x * vv.x + vv.y * vv.y + vv.z * vv.z + vv.w * vv.w;
                r2 += __shfl_xor_sync(0xFFFFFFFFu, r2, 16);
                r2 += __shfl_xor_sync(0xFFFFFFFFu, r2, 8);
                r2 += __shfl_xor_sync(0xFFFFFFFFu, r2, 4);
                r2 += __shfl_xor_sync(0xFFFFFFFFu, r2, 2);
                r2 += __shfl_xor_sync(0xFFFFFFFFu, r2, 1);
                if (lane == 0)
                    g_nrm[(((size_t)(s * 2 + which) * 8 + b) * 512 + rem) * 32 + (n0 >> 7)] = r2;
            }
            __syncthreads();
        }
    }
}

// ---------------------------------------------------------------------------
// Kernel 2a: Gram partials (1-term fp16), double-buffered.
// grid (chunk 8, bh 64, s 2)
// ---------------------------------------------------------------------------
__global__ __launch_bounds__(256) void attn_gram_kernel()
{
    extern __shared__ char dsm[];
    uint32_t sbr = smem_u32(dsm);
    uint32_t sb = (sbr + 1023) & ~1023u;

    const int tid = threadIdx.x;
    const int wid = tid >> 5;
    const int lane = tid & 31;
    const int wm = wid & 1, wn = wid >> 1;
    const int chunk = blockIdx.x;
    const int bh = blockIdx.y;
    const int s = blockIdx.z;
    const int b = bh >> 3, h = bh & 7;
    const int so = s ^ 1;
    const int g = s * 64 + bh;

    const size_t qrow = ((size_t)(s  * 2 + 0) * 8 + b) * 512 + h * 64;
    const size_t krow = ((size_t)(so * 2 + 1) * 8 + b) * 512 + h * 64;

    float acc[2][2][4];
#pragma unroll
    for (int i = 0; i < 2; i++)
#pragma unroll
        for (int j = 0; j < 2; j++)
#pragma unroll
            for (int r = 0; r < 4; r++) acc[i][j][r] = 0.f;

    const int aRow  = wm * 32 + (lane & 15);
    const int aColb = (lane >> 4) * 16;
    const int bRow  = wn * 16 + (lane & 7) + ((lane >> 4) & 1) * 8;
    const int bColb = ((lane >> 3) & 1) * 16;

    auto fill_sub = [&](int st, int sub) {
        int tp0 = chunk * 256 + sub * 32;
#pragma unroll
        for (int it = 0; it < 2; it++) {
            int idx = tid + it * 256;
            int r = idx >> 3, c16 = idx & 7;
            uint32_t dsw = swz((uint32_t)(r * 128 + c16 * 16));
            CP_ASYNC16(sb + SG_Q(st) + dsw, g_qk_h + (qrow + r) * 2048 + tp0 + c16 * 4);
            CP_ASYNC16(sb + SG_K(st) + dsw, g_qk_h + (krow + r) * 2048 + tp0 + c16 * 4);
        }
        CP_COMMIT();
    };

    fill_sub(0, 0);
    for (int sub = 0; sub < 8; sub++) {
        int st = sub & 1;
        if (sub < 7) fill_sub(st ^ 1, sub + 1);
        if (sub < 7) CP_WAIT1(); else CP_WAIT0();
        __syncthreads();
#pragma unroll
        for (int kk = 0; kk < 4; kk++) {
            uint32_t qh[2][4], kf[2][2];
#pragma unroll
            for (int mt = 0; mt < 2; mt++)
                ldmx4(qh[mt][0], qh[mt][1], qh[mt][2], qh[mt][3],
                      sb + SG_Q(st) + swz((uint32_t)((aRow + mt * 16) * 128 + aColb + kk * 32)));
            ldmx4(kf[0][0], kf[0][1], kf[1][0], kf[1][1],
                  sb + SG_K(st) + swz((uint32_t)(bRow * 128 + bColb + kk * 32)));
#pragma unroll
            for (int mt = 0; mt < 2; mt++)
#pragma unroll
                for (int nt = 0; nt < 2; nt++)
                    mma_h(acc[mt][nt], qh[mt], kf[nt]);
        }
        __syncthreads();
    }

    const size_t base = (size_t)(g * 8 + chunk) * 4096;
#pragma unroll
    for (int mt = 0; mt < 2; mt++)
#pragma unroll
        for (int nt = 0; nt < 2; nt++) {
            int m = wm * 32 + mt * 16 + (lane >> 2);
            int col = wn * 16 + nt * 8 + 2 * (lane & 3);
            *(float2*)&g_pgram[base + m * 64 + col] = make_float2(acc[mt][nt][0], acc[mt][nt][1]);
            *(float2*)&g_pgram[base + (m + 8) * 64 + col] = make_float2(acc[mt][nt][2], acc[mt][nt][3]);
        }
}

// ---------------------------------------------------------------------------
// Kernel 2b: reduce partials + norms, softmax (warp-parallel), emit P fp16
// ---------------------------------------------------------------------------
__global__ __launch_bounds__(256) void attn_softmax_kernel(
    const float* __restrict__ temp_rgb, const float* __restrict__ temp_T)
{
    const int g = blockIdx.x;
    const int s = g >> 6;
    const int bh = g & 63;
    const int b = bh >> 3, h = bh & 7;
    const int so = s ^ 1;
    const float temp = (s ? temp_T : temp_rgb)[h];

    __shared__ float qinv[64], kinv[64];
    const int tid = threadIdx.x;

    if (tid < 64) {
        float sq = 0.f;
        size_t nb = (((size_t)(s * 2 + 0) * 8 + b) * 512 + h * 64 + tid) * 32;
#pragma unroll
        for (int t = 0; t < 32; t++) sq += g_nrm[nb + t];
        qinv[tid] = 1.f / fmaxf(sqrtf(sq), 1e-12f);
    } else if (tid < 128) {
        float sk = 0.f;
        size_t nb = (((size_t)(so * 2 + 1) * 8 + b) * 512 + h * 64 + tid - 64) * 32;
#pragma unroll
        for (int t = 0; t < 32; t++) sk += g_nrm[nb + t];
        kinv[tid - 64] = 1.f / fmaxf(sqrtf(sk), 1e-12f);
    }
    __syncthreads();

    const int wid = tid >> 5, lane = tid & 31;
    const int j0 = lane * 2;
    const float ki0 = kinv[j0], ki1 = kinv[j0 + 1];
#pragma unroll
    for (int r = 0; r < 8; r++) {
        int d = wid * 8 + r;
        float v0 = 0.f, v1 = 0.f;
#pragma unroll
        for (int c = 0; c < 8; c++) {
            float2 pv = *(const float2*)&g_pgram[(size_t)(g * 8 + c) * 4096 + d * 64 + j0];
            v0 += pv.x; v1 += pv.y;
        }
        float sc = temp * qinv[d];
        v0 *= sc * ki0;
        v1 *= sc * ki1;
        float mx = fmaxf(v0, v1);
#pragma unroll
        for (int o = 16; o; o >>= 1) mx = fmaxf(mx, __shfl_xor_sync(0xFFFFFFFFu, mx, o));
        float e0 = __expf(v0 - mx), e1 = __expf(v1 - mx);
        float sm = e0 + e1;
#pragma unroll
        for (int o = 16; o; o >>= 1) sm += __shfl_xor_sync(0xFFFFFFFFu, sm, o);
        float inv = 1.f / sm;
        g_p_h[(size_t)g * 2048 + d * 32 + lane] = cvt1h(e0 * inv, e1 * inv);
    }
}

// ---------------------------------------------------------------------------
// Kernel 2c: out = P @ v (1-term). grid (tile 32, bh 64, s 2)
// ---------------------------------------------------------------------------
__global__ __launch_bounds__(256) void attn_pv_kernel()
{
    extern __shared__ char dsm[];
    uint32_t sbr = smem_u32(dsm);
    uint32_t sb = (sbr + 1023) & ~1023u;

    const int tid = threadIdx.x;
    const int wid = tid >> 5;
    const int lane = tid & 31;
    const int wm = wid & 1, wn = wid >> 1;
    const int n0 = blockIdx.x * 128;
    const int bh = blockIdx.y;
    const int s = blockIdx.z;
    const int b = bh >> 3, h = bh & 7;
    const int so = s ^ 1;
    const int g = s * 64 + bh;
    const size_t vb = (size_t)(so * 8 + b) * 4096;

#pragma unroll
    for (int it = 0; it < 4; it++) {
        int idx = tid + it * 256;
        int r = idx >> 3, c16 = idx & 7;
        uint32_t dsw = swz((uint32_t)(r * 128 + c16 * 16));
        CP_ASYNC16(sb + SP_V + dsw, g_v_h + (vb + n0 + r) * 256 + h * 32 + c16 * 4);
    }
#pragma unroll
    for (int it = 0; it < 2; it++) {
        int idx = tid + it * 256;
        int r = idx >> 3, c16 = idx & 7;
        uint32_t dsw = swz((uint32_t)(r * 128 + c16 * 16));
        CP_ASYNC16(sb + SP_P + dsw, g_p_h + (size_t)g * 2048 + r * 32 + c16 * 4);
    }
    CP_COMMIT();
    CP_WAIT0();
    __syncthreads();

    float acc[4][2][4];
#pragma unroll
    for (int i = 0; i < 4; i++)
#pragma unroll
        for (int j = 0; j < 2; j++)
#pragma unroll
            for (int r = 0; r < 4; r++) acc[i][j][r] = 0.f;

    const int aRow  = wm * 64 + (lane & 15);
    const int aColb = (lane >> 4) * 16;
    const int bRow  = wn * 16 + (lane & 7) + ((lane >> 4) & 1) * 8;
    const int bColb = ((lane >> 3) & 1) * 16;

#pragma unroll
    for (int kk = 0; kk < 4; kk++) {
        uint32_t vh[4][4], pf[2][2];
#pragma unroll
        for (int mt = 0; mt < 4; mt++)
            ldmx4(vh[mt][0], vh[mt][1], vh[mt][2], vh[mt][3],
                  sb + SP_V + swz((uint32_t)((aRow + mt * 16) * 128 + aColb + kk * 32)));
        ldmx4(pf[0][0], pf[0][1], pf[1][0], pf[1][1],
              sb + SP_P + swz((uint32_t)(bRow * 128 + bColb + kk * 32)));
#pragma unroll
        for (int mt = 0; mt < 4; mt++)
#pragma unroll
            for (int nt = 0; nt < 2; nt++)
                mma_h(acc[mt][nt], vh[mt], pf[nt]);
    }

    const size_t ob = (size_t)(s * 8 + b) * 4096;
#pragma unroll
    for (int mt = 0; mt < 4; mt++) {
        int t = n0 + wm * 64 + mt * 16 + (lane >> 2);
#pragma unroll
        for (int nt = 0; nt < 2; nt++) {
            int dp = wn * 8 + nt * 4 + (lane & 3);
            size_t a0 = (ob + t) * 256 + h * 32 + dp;
            g_att_h[a0]           = cvt1h(acc[mt][nt][0], acc[mt][nt][1]);
            g_att_h[a0 + 8 * 256] = cvt1h(acc[mt][nt][2], acc[mt][nt][3]);
        }
    }
}

// ---------------------------------------------------------------------------
// Kernel 3: proj GEMM. grid (cTile 2, nTile 32, sb 16)
// ---------------------------------------------------------------------------
__global__ __launch_bounds__(256, 1) void proj_mma_kernel(
    const float* __restrict__ br, const float* __restrict__ bt,
    float* __restrict__ out)
{
    extern __shared__ char dsm[];
    uint32_t sbr = smem_u32(dsm);
    uint32_t sb = (sbr + 1023) & ~1023u;
    char* ab = dsm + (sb - sbr);

    const int tid = threadIdx.x;
    const int wid = tid >> 5;
    const int lane = tid & 31;
    const int wm = wid & 1, wn = wid >> 1;
    const int z = blockIdx.z;
    const int s = z >> 3, b = z & 7;
    const float* __restrict__ bias = s ? bt : br;
    const int n0 = blockIdx.y * 128;
    const int c0 = blockIdx.x * 256;

    const size_t aBase = (((size_t)(s * 8 + b)) * 4096 + n0) * 256;
    const size_t bBase = ((size_t)s * 512 + c0) * 256;

    float acc[4][8][4];
#pragma unroll
    for (int i = 0; i < 4; i++)
#pragma unroll
        for (int j = 0; j < 8; j++)
#pragma unroll
            for (int r = 0; r < 4; r++) acc[i][j][r] = 0.f;

    fill_big(sb, 0, tid, 0, g_att_h, aBase, g_wp_h, bBase);
    fill_big(sb, 1, tid, 32, g_att_h, aBase, g_wp_h, bBase);
    for (int c = 0; c < 8; c++) {
        if (c < 7) CP_WAIT1(); else CP_WAIT0();
        __syncthreads();
        if (c + 2 < 8)
            fill_big(sb, (c + 2) % 3, tid, (c + 2) * 32, g_att_h, aBase, g_wp_h, bBase);
        mma_big(sb, c % 3, wm, wn, lane, acc);
    }
    __syncthreads();

    // epilogue: [token][channel] + bias via smem transpose (2 passes over wm)
    float* sT = (float*)ab;   // 64 x 264 fp32
    float* outp = out + (size_t)(s * 8 + b) * 2097152;
#pragma unroll
    for (int p = 0; p < 2; p++) {
        if (wm == p) {
#pragma unroll
            for (int mt = 0; mt < 4; mt++)
#pragma unroll
                for (int nj = 0; nj < 8; nj++) {
                    int m = mt * 16 + (lane >> 2);
                    int cc = wn * 64 + nj * 8 + 2 * (lane & 3);
                    sT[m * 264 + cc]           = acc[mt][nj][0];
                    sT[m * 264 + cc + 1]       = acc[mt][nj][1];
                    sT[(m + 8) * 264 + cc]     = acc[mt][nj][2];
                    sT[(m + 8) * 264 + cc + 1] = acc[mt][nj][3];
                }
        }
        __syncthreads();
#pragma unroll
        for (int it = 0; it < 16; it++) {
            int idx = tid + it * 256;
            int row = idx >> 6, ch4 = (idx & 63) * 4;
            int tok = n0 + p * 64 + row;
            float4 vv = *(float4*)&sT[row * 264 + ch4];
            float4 bb = *(const float4*)&bias[c0 + ch4];
            vv.x += bb.x; vv.y += bb.y; vv.z += bb.z; vv.w += bb.w;
            *(float4*)&outp[(size_t)tok * 512 + c0 + ch4] = vv;
        }
        __syncthreads();
    }
}

// ---------------------------------------------------------------------------
extern "C" void kernel_launch(void* const* d_in, const int* in_sizes, int n_in,
                              void* d_out, int out_size)
{
    const float* x        = (const float*)d_in[0];
    const float* x_d      = (const float*)d_in[1];
    const float* W_qkv_r  = (const float*)d_in[2];
    const float* W_qkv_T  = (const float*)d_in[3];
    const float* temp_r   = (const float*)d_in[4];
    const float* temp_T   = (const float*)d_in[5];
    const float* W_proj_r = (const float*)d_in[6];
    const float* b_proj_r = (const float*)d_in[7];
    const float* W_proj_T = (const float*)d_in[8];
    const float* b_proj_T = (const float*)d_in[9];
    float* out = (float*)d_out;

    cudaFuncSetAttribute(qkv_mma_kernel,
        cudaFuncAttributeMaxDynamicSharedMemorySize, QKV_SMEM);
    cudaFuncSetAttribute(proj_mma_kernel,
        cudaFuncAttributeMaxDynamicSharedMemorySize, QKV_SMEM);
    cudaFuncSetAttribute(attn_gram_kernel,
        cudaFuncAttributeMaxDynamicSharedMemorySize, GRAM_SMEM);
    cudaFuncSetAttribute(attn_pv_kernel,
        cudaFuncAttributeMaxDynamicSharedMemorySize, PV_SMEM);

    prep_x_kernel<<<65536, 256>>>(x, x_d);
    prep_w_kernel<<<4096, 256>>>(W_qkv_r, W_qkv_T, W_proj_r, W_proj_T);

    {
        dim3 grid(6, 256, 2);     // c-tile fastest -> A slice L2-reused
        qkv_mma_kernel<<<grid, 256, QKV_SMEM>>>();
    }
    {
        dim3 g1(8, 64, 2);
        attn_gram_kernel<<<g1, 256, GRAM_SMEM>>>();
        attn_softmax_kernel<<<128, 256>>>(temp_r, temp_T);
        dim3 g2(32, 64, 2);
        attn_pv_kernel<<<g2, 256, PV_SMEM>>>();
    }
    {
        dim3 grid(2, 32, 16);     // c-tile fastest
        proj_mma_kernel<<<grid, 256, QKV_SMEM>>>(b_proj_r, b_proj_T, out);
    }
}

// round 11
// speedup vs baseline: 1.6637x; 1.0424x over previous
#include <cuda_runtime.h>
#include <cuda_fp16.h>
#include <math.h>
#include <stdint.h>

// ---------------------------------------------------------------------------
// ChannelCrossAttention — HMMA fp16 1-term. Unified token-major scratch:
// q/k/v all stored [s][w][b][n 4096][cpair 256]. qkv epilogue stages through
// smem for coalesced writes; gram uses ldmatrix.trans on token-major tiles.
// ---------------------------------------------------------------------------

// packed 2xfp16 per u32
__device__ uint32_t g_x_h[2u * 32768u * 256u];     // [s][m][kpair]
__device__ uint32_t g_wq_h[2u * 1536u * 256u];     // [s][c][kpair]
__device__ uint32_t g_wp_h[2u * 512u * 256u];
// q/k/v token-major: [s][w 0..2][b][n 4096][cpair 256]
__device__ uint32_t g_qkv_h[2u * 3u * 8u * 4096u * 256u];   // 201 MB
// attention out token-major: [s][b][n][kpair 256]
__device__ uint32_t g_att_h[2u * 8u * 4096u * 256u];
// per-channel sumsq partials: [s][w(q/k)][b][c 512][part 64]
__device__ float g_nrm[2u * 2u * 8u * 512u * 64u];
// Gram partials [g 128][chunk 8][64*64]
__device__ float g_pgram[128u * 8u * 4096u];
// P packed fp16 [g][d 64][epair 32]
__device__ uint32_t g_p_h[128u * 2048u];

// ---------------------------------------------------------------------------
__device__ __forceinline__ uint32_t smem_u32(const void* p) {
    uint32_t a;
    asm("{ .reg .u64 t; cvta.to.shared.u64 t, %1; cvt.u32.u64 %0, t; }" : "=r"(a) : "l"(p));
    return a;
}
__device__ __forceinline__ uint32_t swz(uint32_t off) { return off ^ ((off >> 3) & 0x70); }

__device__ __forceinline__ void ldmx4(uint32_t& r0, uint32_t& r1, uint32_t& r2, uint32_t& r3,
                                      uint32_t addr) {
    asm volatile("ldmatrix.sync.aligned.m8n8.x4.shared.b16 {%0,%1,%2,%3}, [%4];"
        : "=r"(r0), "=r"(r1), "=r"(r2), "=r"(r3) : "r"(addr));
}
__device__ __forceinline__ void ldmx4t(uint32_t& r0, uint32_t& r1, uint32_t& r2, uint32_t& r3,
                                       uint32_t addr) {
    asm volatile("ldmatrix.sync.aligned.m8n8.x4.trans.shared.b16 {%0,%1,%2,%3}, [%4];"
        : "=r"(r0), "=r"(r1), "=r"(r2), "=r"(r3) : "r"(addr));
}
__device__ __forceinline__ void mma_h(float* c, const uint32_t* a, const uint32_t* b) {
    asm volatile("mma.sync.aligned.m16n8k16.row.col.f32.f16.f16.f32 "
        "{%0,%1,%2,%3}, {%4,%5,%6,%7}, {%8,%9}, {%0,%1,%2,%3};"
        : "+f"(c[0]), "+f"(c[1]), "+f"(c[2]), "+f"(c[3])
        : "r"(a[0]), "r"(a[1]), "r"(a[2]), "r"(a[3]), "r"(b[0]), "r"(b[1]));
}
#define CP_ASYNC16(dst, src) \
    asm volatile("cp.async.cg.shared.global [%0], [%1], 16;" :: "r"(dst), "l"(src))
#define CP_COMMIT() asm volatile("cp.async.commit_group;")
#define CP_WAIT0()  asm volatile("cp.async.wait_group 0;")
#define CP_WAIT1()  asm volatile("cp.async.wait_group 1;")

__device__ __forceinline__ uint32_t packh(__half a, __half b) {
    return (uint32_t)__half_as_ushort(a) | ((uint32_t)__half_as_ushort(b) << 16);
}
__device__ __forceinline__ uint32_t cvt1h(float a, float b) {
    return packh(__float2half_rn(a), __float2half_rn(b));
}

// qkv/proj smem: stage = A 16K | B 32K = 48KB, 3 stages (epilogue reuses base)
#define SQ_A(st) ((st) * 49152 + 0)
#define SQ_B(st) ((st) * 49152 + 16384)
#define QKV_SMEM (147456 + 1024)
// gram smem: stage = q 8K | k 8K = 16KB, 2 stages
#define SG_Q(st) ((st) * 16384 + 0)
#define SG_K(st) ((st) * 16384 + 8192)
#define GRAM_SMEM (32768 + 1024)
// pv smem: v 16K | P 8K
#define SP_V 0
#define SP_P 16384
#define PV_SMEM (24576 + 1024)

// ---------------------------------------------------------------------------
// Prep kernels
// ---------------------------------------------------------------------------
__global__ __launch_bounds__(256) void prep_x_kernel(
    const float* __restrict__ x, const float* __restrict__ x_d)
{
    int idx = blockIdx.x * 256 + threadIdx.x;
    int s = idx >> 23;
    int r = idx & 0x7FFFFF;
    int m = r >> 8, kp = r & 255;
    const float* X = s ? x_d : x;
    float2 v = *(const float2*)&X[(size_t)m * 512 + kp * 2];
    g_x_h[idx] = cvt1h(v.x, v.y);
}

__global__ __launch_bounds__(256) void prep_w_kernel(
    const float* __restrict__ Wq_r, const float* __restrict__ Wq_T,
    const float* __restrict__ Wp_r, const float* __restrict__ Wp_T)
{
    int idx = blockIdx.x * 256 + threadIdx.x;
    const int TQ = 2 * 1536 * 256;
    const int TP = 2 * 512 * 256;
    if (idx < TQ) {
        int s = idx / (1536 * 256);
        int r = idx % (1536 * 256);
        int c = r >> 8, kp = r & 255;
        const float* W = s ? Wq_T : Wq_r;
        g_wq_h[idx] = cvt1h(W[(size_t)(2 * kp) * 1536 + c],
                            W[(size_t)(2 * kp + 1) * 1536 + c]);
    } else if (idx < TQ + TP) {
        int i2 = idx - TQ;
        int s = i2 / (512 * 256);
        int r = i2 % (512 * 256);
        int c = r >> 8, kp = r & 255;
        const float* W = s ? Wp_T : Wp_r;
        g_wp_h[i2] = cvt1h(W[(size_t)(2 * kp) * 512 + c],
                           W[(size_t)(2 * kp + 1) * 512 + c]);
    }
}

// ---------------------------------------------------------------------------
// Big-tile GEMM core: CTA 128(m) x 256(n), warp 64x64 (wm 2 x wn 4).
// ---------------------------------------------------------------------------
__device__ __forceinline__ void fill_big(uint32_t sb, int st, int tid, int kp0,
    const uint32_t* __restrict__ A, size_t aBase,
    const uint32_t* __restrict__ B, size_t bBase)
{
#pragma unroll
    for (int it = 0; it < 4; it++) {
        int idx = tid + it * 256;
        int r = idx >> 3, c16 = idx & 7;
        uint32_t dsw = swz((uint32_t)(r * 128 + c16 * 16));
        CP_ASYNC16(sb + SQ_A(st) + dsw, A + aBase + (size_t)r * 256 + kp0 + c16 * 4);
    }
#pragma unroll
    for (int it = 0; it < 8; it++) {
        int idx = tid + it * 256;
        int r = idx >> 3, c16 = idx & 7;
        uint32_t dsw = swz((uint32_t)(r * 128 + c16 * 16));
        CP_ASYNC16(sb + SQ_B(st) + dsw, B + bBase + (size_t)r * 256 + kp0 + c16 * 4);
    }
    CP_COMMIT();
}

__device__ __forceinline__ void mma_big(uint32_t sb, int st, int wm, int wn, int lane,
                                        float acc[4][8][4])
{
    const int aRow  = wm * 64 + (lane & 15);
    const int aColb = (lane >> 4) * 16;
    const int bRow  = wn * 64 + (lane & 7) + ((lane >> 4) & 1) * 8;
    const int bColb = ((lane >> 3) & 1) * 16;
#pragma unroll
    for (int kk = 0; kk < 4; kk++) {
        uint32_t ah[4][4], bf[8][2];
#pragma unroll
        for (int mt = 0; mt < 4; mt++)
            ldmx4(ah[mt][0], ah[mt][1], ah[mt][2], ah[mt][3],
                  sb + SQ_A(st) + swz((uint32_t)((aRow + mt * 16) * 128 + aColb + kk * 32)));
#pragma unroll
        for (int j = 0; j < 4; j++)
            ldmx4(bf[2 * j][0], bf[2 * j][1], bf[2 * j + 1][0], bf[2 * j + 1][1],
                  sb + SQ_B(st) + swz((uint32_t)((bRow + j * 16) * 128 + bColb + kk * 32)));
#pragma unroll
        for (int mt = 0; mt < 4; mt++)
#pragma unroll
            for (int nj = 0; nj < 8; nj++)
                mma_h(acc[mt][nj], ah[mt], bf[nj]);
    }
}

// ---------------------------------------------------------------------------
// Kernel 1: qkv GEMM.  grid (cTile 6, mTile 256, s 2)
// ---------------------------------------------------------------------------
__global__ __launch_bounds__(256, 1) void qkv_mma_kernel()
{
    extern __shared__ char dsm[];
    uint32_t sbr = smem_u32(dsm);
    uint32_t sb = (sbr + 1023) & ~1023u;
    char* ab = dsm + (sb - sbr);

    const int tid = threadIdx.x;
    const int wid = tid >> 5;
    const int lane = tid & 31;
    const int wm = wid & 1, wn = wid >> 1;
    const int s = blockIdx.z;
    const int m0 = blockIdx.y * 128;
    const int c0 = blockIdx.x * 256;
    const int b = m0 >> 12, n0 = m0 & 4095;
    const int which = c0 >> 9;          // 0=q 1=k 2=v

    const size_t aBase = ((size_t)s * 32768 + m0) * 256;
    const size_t bBase = ((size_t)s * 1536 + c0) * 256;

    float acc[4][8][4];
#pragma unroll
    for (int i = 0; i < 4; i++)
#pragma unroll
        for (int j = 0; j < 8; j++)
#pragma unroll
            for (int r = 0; r < 4; r++) acc[i][j][r] = 0.f;

    fill_big(sb, 0, tid, 0, g_x_h, aBase, g_wq_h, bBase);
    fill_big(sb, 1, tid, 32, g_x_h, aBase, g_wq_h, bBase);
    for (int c = 0; c < 8; c++) {
        if (c < 7) CP_WAIT1(); else CP_WAIT0();
        __syncthreads();
        if (c + 2 < 8)
            fill_big(sb, (c + 2) % 3, tid, (c + 2) * 32, g_x_h, aBase, g_wq_h, bBase);
        mma_big(sb, c % 3, wm, wn, lane, acc);
    }
    __syncthreads();   // stage smem free; sbuf reuses it

    // epilogue: frags -> sbuf[t 128][cp 128] (pitch 132) + exact norms for q/k
    uint32_t* sbuf = (uint32_t*)ab;
    const int cb512 = c0 - which * 512;
    const size_t rb = ((size_t)((s * 3 + which) * 8 + b)) * 4096;

#pragma unroll
    for (int nj = 0; nj < 8; nj++) {
        float r2a = 0.f, r2b = 0.f;
#pragma unroll
        for (int mt = 0; mt < 4; mt++) {
            int tl = wm * 64 + mt * 16 + (lane >> 2);
            int cpl = wn * 32 + nj * 4 + (lane & 3);     // local cpair 0..127
            sbuf[tl * 132 + cpl]       = cvt1h(acc[mt][nj][0], acc[mt][nj][1]);
            sbuf[(tl + 8) * 132 + cpl] = cvt1h(acc[mt][nj][2], acc[mt][nj][3]);
            if (which < 2) {
                r2a += acc[mt][nj][0] * acc[mt][nj][0] + acc[mt][nj][2] * acc[mt][nj][2];
                r2b += acc[mt][nj][1] * acc[mt][nj][1] + acc[mt][nj][3] * acc[mt][nj][3];
            }
        }
        if (which < 2) {
            r2a += __shfl_xor_sync(0xFFFFFFFFu, r2a, 4);
            r2b += __shfl_xor_sync(0xFFFFFFFFu, r2b, 4);
            r2a += __shfl_xor_sync(0xFFFFFFFFu, r2a, 8);
            r2b += __shfl_xor_sync(0xFFFFFFFFu, r2b, 8);
            r2a += __shfl_xor_sync(0xFFFFFFFFu, r2a, 16);
            r2b += __shfl_xor_sync(0xFFFFFFFFu, r2b, 16);
            if (lane < 4) {
                int cch = cb512 + wn * 64 + nj * 8 + 2 * lane;
                int part = (n0 >> 7) * 2 + wm;
                size_t nb = ((((size_t)(s * 2 + which)) * 8 + b) * 512 + cch) * 64 + part;
                g_nrm[nb]      = r2a;
                g_nrm[nb + 64] = r2b;
            }
        }
    }
    __syncthreads();

    // coalesced copy sbuf -> g_qkv_h (512B per warp-row segment)
    const int cp0 = cb512 >> 1;     // 0 or 128
#pragma unroll
    for (int it = 0; it < 16; it++) {
        int idx = tid + it * 256;       // 4096 x 16B chunks
        int row = idx >> 5;
        int q4 = idx & 31;
        uint4 v4 = *(uint4*)&sbuf[row * 132 + q4 * 4];
        *(uint4*)&g_qkv_h[(rb + n0 + row) * 256 + cp0 + q4 * 4] = v4;
    }
}

// ---------------------------------------------------------------------------
// Kernel 2a: Gram partials via ldmatrix.trans on token-major q/k.
// grid (chunk 8, bh 64, s 2)
// ---------------------------------------------------------------------------
__global__ __launch_bounds__(256) void attn_gram_kernel()
{
    extern __shared__ char dsm[];
    uint32_t sbr = smem_u32(dsm);
    uint32_t sb = (sbr + 1023) & ~1023u;

    const int tid = threadIdx.x;
    const int wid = tid >> 5;
    const int lane = tid & 31;
    const int wm = wid & 1, wn = wid >> 1;
    const int chunk = blockIdx.x;
    const int bh = blockIdx.y;
    const int s = blockIdx.z;
    const int b = bh >> 3, h = bh & 7;
    const int so = s ^ 1;
    const int g = s * 64 + bh;

    const size_t qb = ((size_t)((s  * 3 + 0) * 8 + b)) * 4096;
    const size_t kb = ((size_t)((so * 3 + 1) * 8 + b)) * 4096;

    float acc[2][2][4];
#pragma unroll
    for (int i = 0; i < 2; i++)
#pragma unroll
        for (int j = 0; j < 2; j++)
#pragma unroll
            for (int r = 0; r < 4; r++) acc[i][j][r] = 0.f;

    auto fill_sub = [&](int st, int sub) {
        int tok0 = chunk * 512 + sub * 64;
#pragma unroll
        for (int it = 0; it < 2; it++) {
            int idx = tid + it * 256;
            int r = idx >> 3, c16 = idx & 7;
            uint32_t dsw = swz((uint32_t)(r * 128 + c16 * 16));
            CP_ASYNC16(sb + SG_Q(st) + dsw, g_qkv_h + (qb + tok0 + r) * 256 + h * 32 + c16 * 4);
            CP_ASYNC16(sb + SG_K(st) + dsw, g_qkv_h + (kb + tok0 + r) * 256 + h * 32 + c16 * 4);
        }
        CP_COMMIT();
    };

    // trans-ldmatrix lane addressing (tiles are [t 64][c 64] fp16, 128B rows)
    const int aTrowOff = ((lane >> 4) & 1) * 8 + (lane & 7);   // A: t +8 for groups 2,3
    const int aDcolOff = ((lane >> 3) & 1) * 8;                // A: d +8 for groups 1,3
    const int bTrowOff = ((lane >> 3) & 1) * 8 + (lane & 7);   // B: t +8 for groups 1,3
    const int bEcolOff = ((lane >> 4) & 1) * 8;                // B: e +8 for groups 2,3

    fill_sub(0, 0);
    for (int sub = 0; sub < 8; sub++) {
        int st = sub & 1;
        if (sub < 7) fill_sub(st ^ 1, sub + 1);
        if (sub < 7) CP_WAIT1(); else CP_WAIT0();
        __syncthreads();
#pragma unroll
        for (int kk = 0; kk < 4; kk++) {
            const int t0 = kk * 16;
            uint32_t qh[2][4], kf[2][2];
#pragma unroll
            for (int mt = 0; mt < 2; mt++) {
                int d0 = wm * 32 + mt * 16;
                ldmx4t(qh[mt][0], qh[mt][1], qh[mt][2], qh[mt][3],
                       sb + SG_Q(st) + swz((uint32_t)((t0 + aTrowOff) * 128 + (d0 + aDcolOff) * 2)));
            }
            {
                int e0 = wn * 16;
                ldmx4t(kf[0][0], kf[0][1], kf[1][0], kf[1][1],
                       sb + SG_K(st) + swz((uint32_t)((t0 + bTrowOff) * 128 + (e0 + bEcolOff) * 2)));
            }
#pragma unroll
            for (int mt = 0; mt < 2; mt++)
#pragma unroll
                for (int nt = 0; nt < 2; nt++)
                    mma_h(acc[mt][nt], qh[mt], kf[nt]);
        }
        __syncthreads();
    }

    const size_t base = (size_t)(g * 8 + chunk) * 4096;
#pragma unroll
    for (int mt = 0; mt < 2; mt++)
#pragma unroll
        for (int nt = 0; nt < 2; nt++) {
            int m = wm * 32 + mt * 16 + (lane >> 2);
            int col = wn * 16 + nt * 8 + 2 * (lane & 3);
            *(float2*)&g_pgram[base + m * 64 + col] = make_float2(acc[mt][nt][0], acc[mt][nt][1]);
            *(float2*)&g_pgram[base + (m + 8) * 64 + col] = make_float2(acc[mt][nt][2], acc[mt][nt][3]);
        }
}

// ---------------------------------------------------------------------------
// Kernel 2b: reduce partials + norms, softmax (warp-parallel), emit P fp16
// ---------------------------------------------------------------------------
__global__ __launch_bounds__(256) void attn_softmax_kernel(
    const float* __restrict__ temp_rgb, const float* __restrict__ temp_T)
{
    const int g = blockIdx.x;
    const int s = g >> 6;
    const int bh = g & 63;
    const int b = bh >> 3, h = bh & 7;
    const int so = s ^ 1;
    const float temp = (s ? temp_T : temp_rgb)[h];

    __shared__ float qinv[64], kinv[64];
    const int tid = threadIdx.x;

    if (tid < 64) {
        float sq = 0.f;
        size_t nb = (((size_t)(s * 2 + 0) * 8 + b) * 512 + h * 64 + tid) * 64;
#pragma unroll
        for (int t = 0; t < 64; t++) sq += g_nrm[nb + t];
        qinv[tid] = 1.f / fmaxf(sqrtf(sq), 1e-12f);
    } else if (tid < 128) {
        float sk = 0.f;
        size_t nb = (((size_t)(so * 2 + 1) * 8 + b) * 512 + h * 64 + tid - 64) * 64;
#pragma unroll
        for (int t = 0; t < 64; t++) sk += g_nrm[nb + t];
        kinv[tid - 64] = 1.f / fmaxf(sqrtf(sk), 1e-12f);
    }
    __syncthreads();

    const int wid = tid >> 5, lane = tid & 31;
    const int j0 = lane * 2;
    const float ki0 = kinv[j0], ki1 = kinv[j0 + 1];
#pragma unroll
    for (int r = 0; r < 8; r++) {
        int d = wid * 8 + r;
        float v0 = 0.f, v1 = 0.f;
#pragma unroll
        for (int c = 0; c < 8; c++) {
            float2 pv = *(const float2*)&g_pgram[(size_t)(g * 8 + c) * 4096 + d * 64 + j0];
            v0 += pv.x; v1 += pv.y;
        }
        float sc = temp * qinv[d];
        v0 *= sc * ki0;
        v1 *= sc * ki1;
        float mx = fmaxf(v0, v1);
#pragma unroll
        for (int o = 16; o; o >>= 1) mx = fmaxf(mx, __shfl_xor_sync(0xFFFFFFFFu, mx, o));
        float e0 = __expf(v0 - mx), e1 = __expf(v1 - mx);
        float sm = e0 + e1;
#pragma unroll
        for (int o = 16; o; o >>= 1) sm += __shfl_xor_sync(0xFFFFFFFFu, sm, o);
        float inv = 1.f / sm;
        g_p_h[(size_t)g * 2048 + d * 32 + lane] = cvt1h(e0 * inv, e1 * inv);
    }
}

// ---------------------------------------------------------------------------
// Kernel 2c: out = P @ v. grid (tile 32, bh 64, s 2)
// ---------------------------------------------------------------------------
__global__ __launch_bounds__(256) void attn_pv_kernel()
{
    extern __shared__ char dsm[];
    uint32_t sbr = smem_u32(dsm);
    uint32_t sb = (sbr + 1023) & ~1023u;

    const int tid = threadIdx.x;
    const int wid = tid >> 5;
    const int lane = tid & 31;
    const int wm = wid & 1, wn = wid >> 1;
    const int n0 = blockIdx.x * 128;
    const int bh = blockIdx.y;
    const int s = blockIdx.z;
    const int b = bh >> 3, h = bh & 7;
    const int so = s ^ 1;
    const int g = s * 64 + bh;
    const size_t vb = ((size_t)((so * 3 + 2) * 8 + b)) * 4096;

#pragma unroll
    for (int it = 0; it < 4; it++) {
        int idx = tid + it * 256;
        int r = idx >> 3, c16 = idx & 7;
        uint32_t dsw = swz((uint32_t)(r * 128 + c16 * 16));
        CP_ASYNC16(sb + SP_V + dsw, g_qkv_h + (vb + n0 + r) * 256 + h * 32 + c16 * 4);
    }
#pragma unroll
    for (int it = 0; it < 2; it++) {
        int idx = tid + it * 256;
        int r = idx >> 3, c16 = idx & 7;
        uint32_t dsw = swz((uint32_t)(r * 128 + c16 * 16));
        CP_ASYNC16(sb + SP_P + dsw, g_p_h + (size_t)g * 2048 + r * 32 + c16 * 4);
    }
    CP_COMMIT();
    CP_WAIT0();
    __syncthreads();

    float acc[4][2][4];
#pragma unroll
    for (int i = 0; i < 4; i++)
#pragma unroll
        for (int j = 0; j < 2; j++)
#pragma unroll
            for (int r = 0; r < 4; r++) acc[i][j][r] = 0.f;

    const int aRow  = wm * 64 + (lane & 15);
    const int aColb = (lane >> 4) * 16;
    const int bRow  = wn * 16 + (lane & 7) + ((lane >> 4) & 1) * 8;
    const int bColb = ((lane >> 3) & 1) * 16;

#pragma unroll
    for (int kk = 0; kk < 4; kk++) {
        uint32_t vh[4][4], pf[2][2];
#pragma unroll
        for (int mt = 0; mt < 4; mt++)
            ldmx4(vh[mt][0], vh[mt][1], vh[mt][2], vh[mt][3],
                  sb + SP_V + swz((uint32_t)((aRow + mt * 16) * 128 + aColb + kk * 32)));
        ldmx4(pf[0][0], pf[0][1], pf[1][0], pf[1][1],
              sb + SP_P + swz((uint32_t)(bRow * 128 + bColb + kk * 32)));
#pragma unroll
        for (int mt = 0; mt < 4; mt++)
#pragma unroll
            for (int nt = 0; nt < 2; nt++)
                mma_h(acc[mt][nt], vh[mt], pf[nt]);
    }

    const size_t ob = (size_t)(s * 8 + b) * 4096;
#pragma unroll
    for (int mt = 0; mt < 4; mt++) {
        int t = n0 + wm * 64 + mt * 16 + (lane >> 2);
#pragma unroll
        for (int nt = 0; nt < 2; nt++) {
            int dp = wn * 8 + nt * 4 + (lane & 3);
            size_t a0 = (ob + t) * 256 + h * 32 + dp;
            g_att_h[a0]           = cvt1h(acc[mt][nt][0], acc[mt][nt][1]);
            g_att_h[a0 + 8 * 256] = cvt1h(acc[mt][nt][2], acc[mt][nt][3]);
        }
    }
}

// ---------------------------------------------------------------------------
// Kernel 3: proj GEMM. grid (cTile 2, nTile 32, sb 16)
// ---------------------------------------------------------------------------
__global__ __launch_bounds__(256, 1) void proj_mma_kernel(
    const float* __restrict__ br, const float* __restrict__ bt,
    float* __restrict__ out)
{
    extern __shared__ char dsm[];
    uint32_t sbr = smem_u32(dsm);
    uint32_t sb = (sbr + 1023) & ~1023u;
    char* ab = dsm + (sb - sbr);

    const int tid = threadIdx.x;
    const int wid = tid >> 5;
    const int lane = tid & 31;
    const int wm = wid & 1, wn = wid >> 1;
    const int z = blockIdx.z;
    const int s = z >> 3, b = z & 7;
    const float* __restrict__ bias = s ? bt : br;
    const int n0 = blockIdx.y * 128;
    const int c0 = blockIdx.x * 256;

    const size_t aBase = (((size_t)(s * 8 + b)) * 4096 + n0) * 256;
    const size_t bBase = ((size_t)s * 512 + c0) * 256;

    float acc[4][8][4];
#pragma unroll
    for (int i = 0; i < 4; i++)
#pragma unroll
        for (int j = 0; j < 8; j++)
#pragma unroll
            for (int r = 0; r < 4; r++) acc[i][j][r] = 0.f;

    fill_big(sb, 0, tid, 0, g_att_h, aBase, g_wp_h, bBase);
    fill_big(sb, 1, tid, 32, g_att_h, aBase, g_wp_h, bBase);
    for (int c = 0; c < 8; c++) {
        if (c < 7) CP_WAIT1(); else CP_WAIT0();
        __syncthreads();
        if (c + 2 < 8)
            fill_big(sb, (c + 2) % 3, tid, (c + 2) * 32, g_att_h, aBase, g_wp_h, bBase);
        mma_big(sb, c % 3, wm, wn, lane, acc);
    }
    __syncthreads();

    // epilogue: [token][channel] + bias via smem transpose (2 passes over wm)
    float* sT = (float*)ab;   // 64 x 264 fp32
    float* outp = out + (size_t)(s * 8 + b) * 2097152;
#pragma unroll
    for (int p = 0; p < 2; p++) {
        if (wm == p) {
#pragma unroll
            for (int mt = 0; mt < 4; mt++)
#pragma unroll
                for (int nj = 0; nj < 8; nj++) {
                    int m = mt * 16 + (lane >> 2);
                    int cc = wn * 64 + nj * 8 + 2 * (lane & 3);
                    sT[m * 264 + cc]           = acc[mt][nj][0];
                    sT[m * 264 + cc + 1]       = acc[mt][nj][1];
                    sT[(m + 8) * 264 + cc]     = acc[mt][nj][2];
                    sT[(m + 8) * 264 + cc + 1] = acc[mt][nj][3];
                }
        }
        __syncthreads();
#pragma unroll
        for (int it = 0; it < 16; it++) {
            int idx = tid + it * 256;
            int row = idx >> 6, ch4 = (idx & 63) * 4;
            int tok = n0 + p * 64 + row;
            float4 vv = *(float4*)&sT[row * 264 + ch4];
            float4 bb = *(const float4*)&bias[c0 + ch4];
            vv.x += bb.x; vv.y += bb.y; vv.z += bb.z; vv.w += bb.w;
            *(float4*)&outp[(size_t)tok * 512 + c0 + ch4] = vv;
        }
        __syncthreads();
    }
}

// ---------------------------------------------------------------------------
extern "C" void kernel_launch(void* const* d_in, const int* in_sizes, int n_in,
                              void* d_out, int out_size)
{
    const float* x        = (const float*)d_in[0];
    const float* x_d      = (const float*)d_in[1];
    const float* W_qkv_r  = (const float*)d_in[2];
    const float* W_qkv_T  = (const float*)d_in[3];
    const float* temp_r   = (const float*)d_in[4];
    const float* temp_T   = (const float*)d_in[5];
    const float* W_proj_r = (const float*)d_in[6];
    const float* b_proj_r = (const float*)d_in[7];
    const float* W_proj_T = (const float*)d_in[8];
    const float* b_proj_T = (const float*)d_in[9];
    float* out = (float*)d_out;

    cudaFuncSetAttribute(qkv_mma_kernel,
        cudaFuncAttributeMaxDynamicSharedMemorySize, QKV_SMEM);
    cudaFuncSetAttribute(proj_mma_kernel,
        cudaFuncAttributeMaxDynamicSharedMemorySize, QKV_SMEM);
    cudaFuncSetAttribute(attn_gram_kernel,
        cudaFuncAttributeMaxDynamicSharedMemorySize, GRAM_SMEM);
    cudaFuncSetAttribute(attn_pv_kernel,
        cudaFuncAttributeMaxDynamicSharedMemorySize, PV_SMEM);

    prep_x_kernel<<<65536, 256>>>(x, x_d);
    prep_w_kernel<<<4096, 256>>>(W_qkv_r, W_qkv_T, W_proj_r, W_proj_T);

    {
        dim3 grid(6, 256, 2);     // c-tile fastest -> A slice L2-reused
        qkv_mma_kernel<<<grid, 256, QKV_SMEM>>>();
    }
    {
        dim3 g1(8, 64, 2);
        attn_gram_kernel<<<g1, 256, GRAM_SMEM>>>();
        attn_softmax_kernel<<<128, 256>>>(temp_r, temp_T);
        dim3 g2(32, 64, 2);
        attn_pv_kernel<<<g2, 256, PV_SMEM>>>();
    }
    {
        dim3 grid(2, 32, 16);     // c-tile fastest
        proj_mma_kernel<<<grid, 256, QKV_SMEM>>>(b_proj_r, b_proj_T, out);
    }
}